// round 1
// baseline (speedup 1.0000x reference)
#include <cuda_runtime.h>

#define TILE 32
#define RAD 5
#define LT 42            // TILE + 2*RAD
#define IPITCH 43        // input tile pitch (conflict-free for 4-row x 8-colgroup warps)
#define HPITCH 33        // intermediate pitch (conflict-free stores/loads)
#define IMG_H 512
#define IMG_W 512
#define NTHREADS 256

__device__ double g_sum;

__global__ void zero_kernel() { g_sum = 0.0; }

__global__ __launch_bounds__(NTHREADS) void ssim_kernel(
        const float* __restrict__ A, const float* __restrict__ B) {
    // Gaussian(sigma=1.5, 11 taps), normalized. Compile-time literals -> FFMA-imm.
    constexpr float WGT[11] = {
        0.00102836f, 0.00759876f, 0.03600077f, 0.10936070f, 0.21300554f,
        0.26601172f,
        0.21300554f, 0.10936070f, 0.03600077f, 0.00759876f, 0.00102836f };

    __shared__ float sA[LT * IPITCH];
    __shared__ float sB[LT * IPITCH];
    __shared__ float h1[LT * HPITCH];
    __shared__ float h2[LT * HPITCH];
    __shared__ float hs[LT * HPITCH];
    __shared__ float hd[LT * HPITCH];
    __shared__ float wsum[NTHREADS / 32];

    const int tid = threadIdx.x;
    const int x0 = blockIdx.x * TILE - RAD;
    const int y0 = blockIdx.y * TILE - RAD;
    const size_t planeOff = (size_t)blockIdx.z * (IMG_H * IMG_W);
    const float* __restrict__ pa = A + planeOff;
    const float* __restrict__ pb = B + planeOff;

    // ---- load halo tile (zero padding outside image) ----
    for (int i = tid; i < LT * LT; i += NTHREADS) {
        int r = i / LT;
        int c = i - r * LT;
        int gy = y0 + r, gx = x0 + c;
        float va = 0.f, vb = 0.f;
        if ((unsigned)gy < IMG_H && (unsigned)gx < IMG_W) {
            va = pa[gy * IMG_W + gx];
            vb = pb[gy * IMG_W + gx];
        }
        sA[r * IPITCH + c] = va;
        sB[r * IPITCH + c] = vb;
    }
    __syncthreads();

    // ---- horizontal pass: 42 rows x 8 col-groups, 4 output cols per thread ----
    // Quantities: m1 = conv_h(x), m2 = conv_h(y), ss = conv_h((x+y)^2), dd = conv_h((x-y)^2)
    for (int g = tid; g < LT * (TILE / 4); g += NTHREADS) {
        int cg = g & 7;
        int r = g >> 3;
        int c0 = cg * 4;
        const float* ra = &sA[r * IPITCH + c0];
        const float* rb = &sB[r * IPITCH + c0];
        float m1[4] = {0,0,0,0}, m2[4] = {0,0,0,0};
        float ss[4] = {0,0,0,0}, dd[4] = {0,0,0,0};
        #pragma unroll
        for (int k = 0; k < 14; k++) {
            float x = ra[k], y = rb[k];
            float p = x + y, q = x - y;
            float pp = p * p, qq = q * q;
            #pragma unroll
            for (int u = 0; u < 4; u++) {
                int t = k - u;
                if (t >= 0 && t < 11) {
                    float w = WGT[t];
                    m1[u] = fmaf(w, x,  m1[u]);
                    m2[u] = fmaf(w, y,  m2[u]);
                    ss[u] = fmaf(w, pp, ss[u]);
                    dd[u] = fmaf(w, qq, dd[u]);
                }
            }
        }
        #pragma unroll
        for (int u = 0; u < 4; u++) {
            h1[r * HPITCH + c0 + u] = m1[u];
            h2[r * HPITCH + c0 + u] = m2[u];
            hs[r * HPITCH + c0 + u] = ss[u];
            hd[r * HPITCH + c0 + u] = dd[u];
        }
    }
    __syncthreads();

    // ---- vertical pass + SSIM: each thread owns one column, 4 consecutive rows ----
    const int c  = tid & 31;
    const int r0 = (tid >> 5) * 4;
    float M1[4]={0,0,0,0}, M2[4]={0,0,0,0}, S[4]={0,0,0,0}, D[4]={0,0,0,0};
    #pragma unroll
    for (int k = 0; k < 14; k++) {
        int row = r0 + k;
        float a1 = h1[row * HPITCH + c];
        float a2 = h2[row * HPITCH + c];
        float as = hs[row * HPITCH + c];
        float ad = hd[row * HPITCH + c];
        #pragma unroll
        for (int u = 0; u < 4; u++) {
            int t = k - u;
            if (t >= 0 && t < 11) {
                float w = WGT[t];
                M1[u] = fmaf(w, a1, M1[u]);
                M2[u] = fmaf(w, a2, M2[u]);
                S[u]  = fmaf(w, as, S[u]);
                D[u]  = fmaf(w, ad, D[u]);
            }
        }
    }

    float acc = 0.f;
    const float C1 = 1e-4f;   // 0.01^2
    const float C2 = 9e-4f;   // 0.03^2
    #pragma unroll
    for (int u = 0; u < 4; u++) {
        float mu1 = M1[u], mu2 = M2[u];
        float mu1sq = mu1 * mu1, mu2sq = mu2 * mu2, mu12 = mu1 * mu2;
        // conv(xy) = (S-D)/4 ; conv(x^2)+conv(y^2) = (S+D)/2
        float sig12 = 0.25f * (S[u] - D[u]) - mu12;
        float sigs  = 0.5f  * (S[u] + D[u]) - mu1sq - mu2sq;
        float num = (2.f * mu12 + C1) * (2.f * sig12 + C2);
        float den = (mu1sq + mu2sq + C1) * (sigs + C2);
        acc += __fdividef(num, den);
    }

    // ---- block reduction -> one double atomic per block ----
    #pragma unroll
    for (int o = 16; o > 0; o >>= 1)
        acc += __shfl_xor_sync(0xffffffffu, acc, o);
    if ((tid & 31) == 0) wsum[tid >> 5] = acc;
    __syncthreads();
    if (tid == 0) {
        float t = 0.f;
        #pragma unroll
        for (int wi = 0; wi < NTHREADS / 32; wi++) t += wsum[wi];
        atomicAdd(&g_sum, (double)t);
    }
}

__global__ void final_kernel(float* out, long long n) {
    out[0] = (float)(1.0 - g_sum / (double)n);
}

extern "C" void kernel_launch(void* const* d_in, const int* in_sizes, int n_in,
                              void* d_out, int out_size) {
    const float* A = (const float*)d_in[0];   // clean
    const float* B = (const float*)d_in[1];   // adversarial
    float* out = (float*)d_out;
    long long total = (long long)in_sizes[0];
    int planes = (int)(total / (IMG_H * IMG_W));   // 96 = 32*3

    zero_kernel<<<1, 1>>>();
    dim3 grid(IMG_W / TILE, IMG_H / TILE, planes);
    ssim_kernel<<<grid, NTHREADS>>>(A, B);
    final_kernel<<<1, 1>>>(out, total);
}

// round 3
// speedup vs baseline: 1.0051x; 1.0051x over previous
#include <cuda_runtime.h>

#define TILE 32
#define RAD 5
#define LT 42            // TILE + 2*RAD
#define IP 43            // input tile pitch (in float2/u64 units)
#define HP 33            // intermediate pitch (in float2/u64 units)
#define IMG 512
#define NT 256
#define GRID1D 16        // 512/32
#define NBLK (GRID1D * GRID1D * 96)

typedef unsigned long long u64;

__device__ float g_part[NBLK];

__device__ __forceinline__ u64 pk2(float x, float y) {
    u64 r; asm("mov.b64 %0,{%1,%2};" : "=l"(r) : "f"(x), "f"(y)); return r;
}
__device__ __forceinline__ void upk2(u64 v, float& x, float& y) {
    asm("mov.b64 {%0,%1},%2;" : "=f"(x), "=f"(y) : "l"(v));
}
__device__ __forceinline__ u64 fma2(u64 a, u64 b, u64 c) {
    u64 d; asm("fma.rn.f32x2 %0,%1,%2,%3;" : "=l"(d) : "l"(a), "l"(b), "l"(c)); return d;
}
__device__ __forceinline__ u64 mul2(u64 a, u64 b) {
    u64 d; asm("mul.rn.f32x2 %0,%1,%2;" : "=l"(d) : "l"(a), "l"(b)); return d;
}

__global__ __launch_bounds__(NT) void ssim_kernel(
        const float* __restrict__ A, const float* __restrict__ B) {
    // Gaussian(sigma=1.5, 11 taps), normalized
    constexpr float WGT[11] = {
        0.00102836f, 0.00759876f, 0.03600077f, 0.10936070f, 0.21300554f,
        0.26601172f,
        0.21300554f, 0.10936070f, 0.03600077f, 0.00759876f, 0.00102836f };

    // sPQ holds packed (p,q) = (x+y, x-y) per pixel
    __shared__ u64 sPQ[LT * IP];
    __shared__ u64 hPQ[LT * HP];   // horizontal conv of (p,q)
    __shared__ u64 hSD[LT * HP];   // horizontal conv of (p^2,q^2)
    __shared__ float wsum[NT / 32];

    const int tid = threadIdx.x;
    const int x0 = blockIdx.x * TILE - RAD;
    const int y0 = blockIdx.y * TILE - RAD;
    const size_t planeOff = (size_t)blockIdx.z * (IMG * IMG);
    const float* __restrict__ pa = A + planeOff;
    const float* __restrict__ pb = B + planeOff;

    // ---- load halo tile, build (p,q) packed; zero padding outside image ----
    for (int i = tid; i < LT * LT; i += NT) {
        int r = i / LT;
        int c = i - r * LT;
        int gy = y0 + r, gx = x0 + c;
        float va = 0.f, vb = 0.f;
        if ((unsigned)gy < IMG && (unsigned)gx < IMG) {
            va = pa[gy * IMG + gx];
            vb = pb[gy * IMG + gx];
        }
        sPQ[r * IP + c] = pk2(va + vb, va - vb);
    }
    __syncthreads();

    // ---- horizontal pass: 42 rows x 8 col-groups, 4 consecutive output cols/thread ----
    for (int g = tid; g < LT * (TILE / 4); g += NT) {
        int cg = g & 7;
        int r = g >> 3;
        int c0 = cg * 4;
        const u64* row = &sPQ[r * IP + c0];
        u64 m[4] = {0,0,0,0};   // conv_h(p,q)
        u64 s[4] = {0,0,0,0};   // conv_h(p^2,q^2)
        #pragma unroll
        for (int k = 0; k < 14; k++) {
            u64 v  = row[k];
            u64 vv = mul2(v, v);
            #pragma unroll
            for (int u = 0; u < 4; u++) {
                int t = k - u;
                if (t >= 0 && t < 11) {
                    u64 w = pk2(WGT[t], WGT[t]);
                    m[u] = fma2(w, v,  m[u]);
                    s[u] = fma2(w, vv, s[u]);
                }
            }
        }
        #pragma unroll
        for (int u = 0; u < 4; u++) {
            hPQ[r * HP + c0 + u] = m[u];
            hSD[r * HP + c0 + u] = s[u];
        }
    }
    __syncthreads();

    // ---- vertical pass + SSIM: one column per thread, 4 consecutive rows ----
    const int c  = tid & 31;
    const int r0 = (tid >> 5) * 4;
    u64 M[4] = {0,0,0,0};
    u64 S[4] = {0,0,0,0};
    #pragma unroll
    for (int k = 0; k < 14; k++) {
        int row = r0 + k;
        u64 a = hPQ[row * HP + c];
        u64 b = hSD[row * HP + c];
        #pragma unroll
        for (int u = 0; u < 4; u++) {
            int t = k - u;
            if (t >= 0 && t < 11) {
                u64 w = pk2(WGT[t], WGT[t]);
                M[u] = fma2(w, a, M[u]);
                S[u] = fma2(w, b, S[u]);
            }
        }
    }

    float acc = 0.f;
    const float C1 = 1e-4f;   // 0.01^2
    const float C2 = 9e-4f;   // 0.03^2
    #pragma unroll
    for (int u = 0; u < 4; u++) {
        float Mp, Mq, Sp, Sq;
        upk2(M[u], Mp, Mq);
        upk2(S[u], Sp, Sq);
        float Mp2 = Mp * Mp, Mq2 = Mq * Mq;
        float Ep = Sp - Mp2;       // conv(p^2) - Mp^2
        float Eq = Sq - Mq2;
        // mu12 = (Mp2-Mq2)/4 ; mu1^2+mu2^2 = (Mp2+Mq2)/2
        // sig12 = (Ep-Eq)/4  ; sig1^2+sig2^2 = (Ep+Eq)/2
        float num = (0.5f * (Mp2 - Mq2) + C1) * (0.5f * (Ep - Eq) + C2);
        float den = (0.5f * (Mp2 + Mq2) + C1) * (0.5f * (Ep + Eq) + C2);
        acc += __fdividef(num, den);
    }

    // ---- block reduction -> per-block partial ----
    #pragma unroll
    for (int o = 16; o > 0; o >>= 1)
        acc += __shfl_xor_sync(0xffffffffu, acc, o);
    if ((tid & 31) == 0) wsum[tid >> 5] = acc;
    __syncthreads();
    if (tid == 0) {
        float t = 0.f;
        #pragma unroll
        for (int wi = 0; wi < NT / 32; wi++) t += wsum[wi];
        g_part[(blockIdx.z * GRID1D + blockIdx.y) * GRID1D + blockIdx.x] = t;
    }
}

__global__ void final_kernel(float* out, long long n, int nblk) {
    __shared__ double sh[NT];
    double s = 0.0;
    for (int i = threadIdx.x; i < nblk; i += NT) s += (double)g_part[i];
    sh[threadIdx.x] = s;
    __syncthreads();
    #pragma unroll
    for (int o = NT / 2; o > 0; o >>= 1) {
        if (threadIdx.x < o) sh[threadIdx.x] += sh[threadIdx.x + o];
        __syncthreads();
    }
    if (threadIdx.x == 0) out[0] = (float)(1.0 - sh[0] / (double)n);
}

extern "C" void kernel_launch(void* const* d_in, const int* in_sizes, int n_in,
                              void* d_out, int out_size) {
    const float* A = (const float*)d_in[0];   // clean
    const float* B = (const float*)d_in[1];   // adversarial
    float* out = (float*)d_out;
    long long total = (long long)in_sizes[0];
    int planes = (int)(total / (IMG * IMG));  // 96 = 32*3
    int nblk = GRID1D * GRID1D * planes;

    dim3 grid(GRID1D, GRID1D, planes);
    ssim_kernel<<<grid, NT>>>(A, B);
    final_kernel<<<1, NT>>>(out, total, nblk);
}